// round 4
// baseline (speedup 1.0000x reference)
#include <cuda_runtime.h>
#include <cuda_fp16.h>
#include <cstdint>

// GraphConv: out = relu( ((A @ X + X) / (rowsum(A)+1)) @ W )
// A: [4,4096,4096] f32, X: [4,4096,128] f32, W: [128,128] f32, out f32.
// fp16 mma.sync m16n8k16 path; A converted on the fly, deg exact in f32.

#define Bn 4
#define Nn 4096
#define Fn 128
#define KT 32
#define NTILES (Nn / KT)   // 128
#define BSTAGES 8
#define NTHR 256

// device scratch: X^T per batch [f][k] fp16, W^T [n][k] fp16
__device__ __align__(256) __half Xt_g[(size_t)Bn * Fn * Nn];
__device__ __align__(256) __half Wt_g[Fn * Fn];

// smem layout (bytes):
//  Abuf   2 x 8192   @ 0
//  Bstage 8 x 8192   @ 16384
//  Ws     4 x 8192   @ 81920
//  deg    1024       @ 114688
//  Ys (4 x 8192) reuses @ 0 after mainloop
#define AB_OFF  0
#define BS_OFF  16384
#define WS_OFF  81920
#define DEG_OFF 114688
#define YS_OFF  0
#define SMEM_TOTAL (DEG_OFF + 1024)

#define SW64(x) ((x) ^ (((x) >> 3) & 0x30))

__device__ __forceinline__ uint32_t smem_u32(const void* p) {
    uint32_t a;
    asm("{ .reg .u64 t; cvta.to.shared.u64 t, %1; cvt.u32.u64 %0, t; }" : "=r"(a) : "l"(p));
    return a;
}
__device__ __forceinline__ void cp16(uint32_t dst, const void* src) {
    asm volatile("cp.async.cg.shared.global [%0], [%1], 16;" :: "r"(dst), "l"(src) : "memory");
}
__device__ __forceinline__ void ldsm4(uint32_t* r, uint32_t a) {
    asm volatile("ldmatrix.sync.aligned.m8n8.x4.shared.b16 {%0,%1,%2,%3}, [%4];"
                 : "=r"(r[0]), "=r"(r[1]), "=r"(r[2]), "=r"(r[3]) : "r"(a));
}
__device__ __forceinline__ void mma16(float* c, const uint32_t* a, const uint32_t* b) {
    asm volatile(
        "mma.sync.aligned.m16n8k16.row.col.f32.f16.f16.f32 "
        "{%0,%1,%2,%3},{%4,%5,%6,%7},{%8,%9},{%0,%1,%2,%3};"
        : "+f"(c[0]), "+f"(c[1]), "+f"(c[2]), "+f"(c[3])
        : "r"(a[0]), "r"(a[1]), "r"(a[2]), "r"(a[3]), "r"(b[0]), "r"(b[1]));
}
__device__ __forceinline__ uint32_t packh2(float a, float b) {
    __half2 h = __floats2half2_rn(a, b);
    return *(uint32_t*)&h;
}

// ===================== prep kernels =====================
__global__ void prep_xt(const float* __restrict__ X) {
    __shared__ float t[32][33];
    int b = blockIdx.z;
    int bk = blockIdx.x * 32;   // node (k) tile
    int bn = blockIdx.y * 32;   // feature (n) tile
    int tx = threadIdx.x, ty = threadIdx.y;   // 32 x 8
    const float* Xb = X + (size_t)b * Nn * Fn;
    __half* Xtb = Xt_g + (size_t)b * Fn * Nn;
#pragma unroll
    for (int i = 0; i < 4; i++)
        t[ty + i * 8][tx] = Xb[(size_t)(bk + ty + i * 8) * Fn + bn + tx];
    __syncthreads();
#pragma unroll
    for (int i = 0; i < 4; i++)
        Xtb[(size_t)(bn + ty + i * 8) * Nn + bk + tx] = __float2half_rn(t[tx][ty + i * 8]);
}

__global__ void prep_wt(const float* __restrict__ W) {
    __shared__ float t[32][33];
    int bk = blockIdx.x * 32, bn = blockIdx.y * 32;
    int tx = threadIdx.x, ty = threadIdx.y;
#pragma unroll
    for (int i = 0; i < 4; i++)
        t[ty + i * 8][tx] = W[(size_t)(bk + ty + i * 8) * Fn + bn + tx];
    __syncthreads();
#pragma unroll
    for (int i = 0; i < 4; i++)
        Wt_g[(size_t)(bn + ty + i * 8) * Fn + bk + tx] = __float2half_rn(t[tx][ty + i * 8]);
}

// ===================== main kernel =====================
__global__ __launch_bounds__(NTHR, 1)
void graphconv_mma_kernel(const float* __restrict__ A,
                          const float* __restrict__ X,
                          float* __restrict__ out)
{
    extern __shared__ char smem[];
    const uint32_t sb = smem_u32(smem);
    const int tid = threadIdx.x;
    const int w = tid >> 5, L = tid & 31;
    const int b = blockIdx.y, r0 = blockIdx.x * 128;

    // warp tile m64 x n32 ; warps 2(m) x 4(n)
    const int mw = (w >> 2) * 64;
    const int nw = (w & 3) * 32;
    const int g = L >> 2, tg = L & 3;
    // ldsm lane offsets (fp16, 64B rows)
    const int arow = L & 15;                     // + achk bytes
    const int achk = (L >> 4) * 16;
    const int brow = (L & 7) + ((L >> 4) << 3);
    const int bchk = ((L >> 3) & 1) * 16;
    // A gmem load role: 16 consecutive f32 (half a 128B row)
    const int lrow = tid >> 1;
    const int lh   = tid & 1;

    const float* Abase = A + ((size_t)b * Nn + r0) * Nn;
    const __half* Xth  = Xt_g + (size_t)b * Fn * Nn;

    float acc[16][4];
#pragma unroll
    for (int i = 0; i < 16; i++)
#pragma unroll
        for (int j = 0; j < 4; j++) acc[i][j] = 0.0f;

    float degacc = 0.0f;
    float4 aq[2][4];                // A prefetch queues (2 tiles deep)
    const float* Aldg = Abase + (size_t)lrow * Nn + lh * 16;

    auto ldgA = [&](int t, int buf) {
        const float4* p = (const float4*)(Aldg + t * KT);
#pragma unroll
        for (int i = 0; i < 4; i++) aq[buf][i] = p[i];
    };
    auto cpB = [&](int t) {
        const int s = t & (BSTAGES - 1);
        const int k0 = t * KT;
#pragma unroll
        for (int i = 0; i < 2; i++) {
            int c = tid + i * NTHR;     // 0..511
            int n = c >> 2, j = c & 3;
            cp16(sb + BS_OFF + s * 8192 + SW64(n * 64 + j * 16),
                 Xth + (size_t)n * Nn + k0 + j * 8);
        }
    };
    auto stsA = [&](int buf) {
        float4 q0 = aq[buf][0], q1 = aq[buf][1], q2 = aq[buf][2], q3 = aq[buf][3];
        degacc += (q0.x + q0.y + q0.z + q0.w) + (q1.x + q1.y + q1.z + q1.w)
                + (q2.x + q2.y + q2.z + q2.w) + (q3.x + q3.y + q3.z + q3.w);
        uint32_t base = sb + AB_OFF + buf * 8192;
        uint32_t d0 = base + SW64(lrow * 64 + lh * 32);
        uint32_t d1 = base + SW64(lrow * 64 + lh * 32 + 16);
        asm volatile("st.shared.v4.b32 [%0], {%1,%2,%3,%4};"
            :: "r"(d0), "r"(packh2(q0.x,q0.y)), "r"(packh2(q0.z,q0.w)),
               "r"(packh2(q1.x,q1.y)), "r"(packh2(q1.z,q1.w)) : "memory");
        asm volatile("st.shared.v4.b32 [%0], {%1,%2,%3,%4};"
            :: "r"(d1), "r"(packh2(q2.x,q2.y)), "r"(packh2(q2.z,q2.w)),
               "r"(packh2(q3.x,q3.y)), "r"(packh2(q3.z,q3.w)) : "memory");
    };
    auto compute32 = [&](uint32_t aA, uint32_t aB, float (*ac)[4]) {
#pragma unroll
        for (int kc = 0; kc < 2; kc++) {
            uint32_t af[4][4];
#pragma unroll
            for (int mt = 0; mt < 4; mt++)
                ldsm4(af[mt], aA + SW64((mw + mt * 16 + arow) * 64 + kc * 32 + achk));
            uint32_t bf[4][2];
#pragma unroll
            for (int np = 0; np < 2; np++) {
                uint32_t r[4];
                ldsm4(r, aB + SW64((nw + np * 16 + brow) * 64 + kc * 32 + bchk));
                bf[np * 2][0] = r[0]; bf[np * 2][1] = r[1];
                bf[np * 2 + 1][0] = r[2]; bf[np * 2 + 1][1] = r[3];
            }
#pragma unroll
            for (int mt = 0; mt < 4; mt++)
#pragma unroll
                for (int nt = 0; nt < 4; nt++)
                    mma16(ac[mt * 4 + nt], af[mt], bf[nt]);
        }
    };

    // ---- prologue ----
    ldgA(0, 0); ldgA(1, 1);
#pragma unroll
    for (int t = 0; t < BSTAGES - 1; t++) {   // B0..B6
        if (t < NTILES) cpB(t);
        asm volatile("cp.async.commit_group;" ::: "memory");
    }

    // ---- mainloop ----
    for (int t = 0; t < NTILES; t++) {
        asm volatile("cp.async.wait_group %0;" :: "n"(BSTAGES - 2) : "memory");
        stsA(t & 1);
        __syncthreads();
        if (t + BSTAGES - 1 < NTILES) cpB(t + BSTAGES - 1);
        asm volatile("cp.async.commit_group;" ::: "memory");
        if (t + 2 < NTILES) ldgA(t + 2, t & 1);
        compute32(sb + AB_OFF + (t & 1) * 8192,
                  sb + BS_OFF + (t & (BSTAGES - 1)) * 8192, acc);
    }

    // ---- deg partials + stage W^T (fp16) ----
    float* degp = (float*)(smem + DEG_OFF);
    degp[tid] = degacc;
#pragma unroll
    for (int i = 0; i < 8; i++) {
        int c = tid + i * NTHR;         // 0..2047 chunks of 8 halves
        int n = c >> 4, j = c & 15;
        cp16(sb + WS_OFF + (j >> 2) * 8192 + SW64(n * 64 + (j & 3) * 16),
             Wt_g + (size_t)n * Fn + j * 8);
    }
    asm volatile("cp.async.commit_group;" ::: "memory");
    __syncthreads();   // all compute done (Ys region free), degp visible

    // ---- y = (ax + X) / (deg + 1) -> fp16 smem [4 ktiles][128m][32k] ----
#pragma unroll
    for (int mt = 0; mt < 4; mt++) {
        int m1 = mw + mt * 16 + g, m2 = m1 + 8;
        float r1 = 1.0f / (degp[2 * m1] + degp[2 * m1 + 1] + 1.0f);
        float r2 = 1.0f / (degp[2 * m2] + degp[2 * m2 + 1] + 1.0f);
        const float* x1 = X + ((size_t)b * Nn + r0 + m1) * Fn;
        const float* x2 = X + ((size_t)b * Nn + r0 + m2) * Fn;
#pragma unroll
        for (int nt = 0; nt < 4; nt++) {
            int n = nw + nt * 8 + 2 * tg;
            float* c = acc[mt * 4 + nt];
            float2 xa = *(const float2*)(x1 + n);
            float2 xb = *(const float2*)(x2 + n);
            uint32_t y01 = packh2((c[0] + xa.x) * r1, (c[1] + xa.y) * r1);
            uint32_t y23 = packh2((c[2] + xb.x) * r2, (c[3] + xb.y) * r2);
            uint32_t base = sb + YS_OFF + (n >> 5) * 8192;
            asm volatile("st.shared.b32 [%0], %1;"
                         :: "r"(base + SW64(m1 * 64 + (n & 31) * 2)), "r"(y01) : "memory");
            asm volatile("st.shared.b32 [%0], %1;"
                         :: "r"(base + SW64(m2 * 64 + (n & 31) * 2)), "r"(y23) : "memory");
        }
    }
    asm volatile("cp.async.wait_group 0;" ::: "memory");
    __syncthreads();

    // ---- second GEMM: z = y @ W (M=128,N=128,K=128) ----
    float acc2[16][4];
#pragma unroll
    for (int i = 0; i < 16; i++)
#pragma unroll
        for (int j = 0; j < 4; j++) acc2[i][j] = 0.0f;
#pragma unroll
    for (int kt = 0; kt < 4; kt++)
        compute32(sb + YS_OFF + kt * 8192, sb + WS_OFF + kt * 8192, acc2);

    // ---- relu + store ----
#pragma unroll
    for (int mt = 0; mt < 4; mt++) {
        int m1 = mw + mt * 16 + g, m2 = m1 + 8;
        float* o1 = out + ((size_t)b * Nn + r0 + m1) * Fn;
        float* o2 = out + ((size_t)b * Nn + r0 + m2) * Fn;
#pragma unroll
        for (int nt = 0; nt < 4; nt++) {
            int n = nw + nt * 8 + 2 * tg;
            float* c = acc2[mt * 4 + nt];
            *(float2*)(o1 + n) = make_float2(fmaxf(c[0], 0.0f), fmaxf(c[1], 0.0f));
            *(float2*)(o2 + n) = make_float2(fmaxf(c[2], 0.0f), fmaxf(c[3], 0.0f));
        }
    }
}

// ===================== launch =====================
extern "C" void kernel_launch(void* const* d_in, const int* in_sizes, int n_in,
                              void* d_out, int out_size)
{
    const float* A = (const float*)d_in[0];
    const float* X = (const float*)d_in[1];
    const float* W = (const float*)d_in[2];
    float* out = (float*)d_out;

    static bool attr_set = false;
    if (!attr_set) {
        cudaFuncSetAttribute(graphconv_mma_kernel,
                             cudaFuncAttributeMaxDynamicSharedMemorySize, SMEM_TOTAL);
        attr_set = true;
    }

    dim3 tb(32, 8);
    prep_xt<<<dim3(Nn / 32, Fn / 32, Bn), tb>>>(X);
    prep_wt<<<dim3(Fn / 32, Fn / 32), tb>>>(W);

    dim3 grid(Nn / 128, Bn);
    graphconv_mma_kernel<<<grid, NTHR, SMEM_TOTAL>>>(A, X, out);
}

// round 5
// speedup vs baseline: 1.0394x; 1.0394x over previous
#include <cuda_runtime.h>
#include <cuda_fp16.h>
#include <cstdint>

// GraphConv: out = relu( ((A @ X + X) / (rowsum(A)+1)) @ W )
// A: [4,4096,4096] f32, X: [4,4096,128] f32, W: [128,128] f32, out f32.
// fp16 mma.sync m16n8k16; A ingested via coalesced LDG -> pack -> STS.

#define Bn 4
#define Nn 4096
#define Fn 128
#define KT 32
#define NTILES (Nn / KT)   // 128
#define BSTAGES 8
#define NTHR 256

// device scratch: X^T per batch [f][k] fp16, W^T [n][k] fp16
__device__ __align__(256) __half Xt_g[(size_t)Bn * Fn * Nn];
__device__ __align__(256) __half Wt_g[Fn * Fn];

// smem layout (bytes):
//  Abuf   2 x 8192   @ 0
//  Bstage 8 x 8192   @ 16384
//  Ws     4 x 8192   @ 81920
//  degp   128*8*4    @ 114688
//  Ys (4 x 8192) reuses @ 0 after mainloop
#define AB_OFF  0
#define BS_OFF  16384
#define WS_OFF  81920
#define DEG_OFF 114688
#define YS_OFF  0
#define SMEM_TOTAL (DEG_OFF + 4096)

#define SW64(x) ((x) ^ (((x) >> 3) & 0x30))

__device__ __forceinline__ uint32_t smem_u32(const void* p) {
    uint32_t a;
    asm("{ .reg .u64 t; cvta.to.shared.u64 t, %1; cvt.u32.u64 %0, t; }" : "=r"(a) : "l"(p));
    return a;
}
__device__ __forceinline__ void cp16(uint32_t dst, const void* src) {
    asm volatile("cp.async.cg.shared.global [%0], [%1], 16;" :: "r"(dst), "l"(src) : "memory");
}
__device__ __forceinline__ void ldsm4(uint32_t* r, uint32_t a) {
    asm volatile("ldmatrix.sync.aligned.m8n8.x4.shared.b16 {%0,%1,%2,%3}, [%4];"
                 : "=r"(r[0]), "=r"(r[1]), "=r"(r[2]), "=r"(r[3]) : "r"(a));
}
__device__ __forceinline__ void mma16(float* c, const uint32_t* a, const uint32_t* b) {
    asm volatile(
        "mma.sync.aligned.m16n8k16.row.col.f32.f16.f16.f32 "
        "{%0,%1,%2,%3},{%4,%5,%6,%7},{%8,%9},{%0,%1,%2,%3};"
        : "+f"(c[0]), "+f"(c[1]), "+f"(c[2]), "+f"(c[3])
        : "r"(a[0]), "r"(a[1]), "r"(a[2]), "r"(a[3]), "r"(b[0]), "r"(b[1]));
}
__device__ __forceinline__ uint32_t packh2(float a, float b) {
    __half2 h = __floats2half2_rn(a, b);
    return *(uint32_t*)&h;
}

// ===================== fused prep kernel =====================
// z in [0, Bn): transpose X batch z -> Xt_g fp16.
// z == Bn: transpose W -> Wt_g fp16 (only blockIdx.x<4 && y<4 active).
__global__ void prep_fused(const float* __restrict__ X, const float* __restrict__ W) {
    __shared__ float t[32][33];
    int tx = threadIdx.x, ty = threadIdx.y;   // 32 x 8
    if (blockIdx.z < Bn) {
        int b = blockIdx.z;
        int bk = blockIdx.x * 32;   // node (k) tile
        int bn = blockIdx.y * 32;   // feature (n) tile
        const float* Xb = X + (size_t)b * Nn * Fn;
        __half* Xtb = Xt_g + (size_t)b * Fn * Nn;
#pragma unroll
        for (int i = 0; i < 4; i++)
            t[ty + i * 8][tx] = Xb[(size_t)(bk + ty + i * 8) * Fn + bn + tx];
        __syncthreads();
#pragma unroll
        for (int i = 0; i < 4; i++)
            Xtb[(size_t)(bn + ty + i * 8) * Nn + bk + tx] = __float2half_rn(t[tx][ty + i * 8]);
    } else {
        if (blockIdx.x >= 4 || blockIdx.y >= 4) return;
        int bk = blockIdx.x * 32, bn = blockIdx.y * 32;
#pragma unroll
        for (int i = 0; i < 4; i++)
            t[ty + i * 8][tx] = W[(size_t)(bk + ty + i * 8) * Fn + bn + tx];
        __syncthreads();
#pragma unroll
        for (int i = 0; i < 4; i++)
            Wt_g[(size_t)(bn + ty + i * 8) * Fn + bk + tx] = __float2half_rn(t[tx][ty + i * 8]);
    }
}

// ===================== main kernel =====================
__global__ __launch_bounds__(NTHR, 1)
void graphconv_mma_kernel(const float* __restrict__ A,
                          const float* __restrict__ X,
                          float* __restrict__ out)
{
    extern __shared__ char smem[];
    const uint32_t sb = smem_u32(smem);
    const int tid = threadIdx.x;
    const int w = tid >> 5, L = tid & 31;
    const int b = blockIdx.y, r0 = blockIdx.x * 128;

    // warp tile m64 x n32 ; warps 2(m) x 4(n)
    const int mw = (w >> 2) * 64;
    const int nw = (w & 3) * 32;
    const int g = L >> 2, tg = L & 3;
    // ldsm lane offsets (fp16, 64B rows)
    const int arow = L & 15;
    const int achk = (L >> 4) * 16;
    const int brow = (L & 7) + ((L >> 4) << 3);
    const int bchk = ((L >> 3) & 1) * 16;
    // A gmem load role: coalesced — 8 threads per row, 16B each
    const int arow8 = tid >> 3;   // 0..31 (+32*i)
    const int acol  = tid & 7;    // 16B chunk within 128B row

    const float* Abase = A + ((size_t)b * Nn + r0) * Nn;
    const __half* Xth  = Xt_g + (size_t)b * Fn * Nn;

    float acc[16][4];
#pragma unroll
    for (int i = 0; i < 16; i++)
#pragma unroll
        for (int j = 0; j < 4; j++) acc[i][j] = 0.0f;

    float dega[4] = {0.0f, 0.0f, 0.0f, 0.0f};
    float4 aq[2][4];                // A prefetch queues (2 tiles deep)
    const float* Aldg = Abase + (size_t)arow8 * Nn + acol * 4;

    auto ldgA = [&](int t, int buf) {
#pragma unroll
        for (int i = 0; i < 4; i++)
            aq[buf][i] = *(const float4*)(Aldg + (size_t)(32 * i) * Nn + t * KT);
    };
    auto cpB = [&](int t) {
        const int s = t & (BSTAGES - 1);
        const int k0 = t * KT;
#pragma unroll
        for (int i = 0; i < 2; i++) {
            int c = tid + i * NTHR;     // 0..511
            int n = c >> 2, j = c & 3;
            cp16(sb + BS_OFF + s * 8192 + SW64(n * 64 + j * 16),
                 Xth + (size_t)n * Nn + k0 + j * 8);
        }
    };
    auto stsA = [&](int buf) {
        uint32_t base = sb + AB_OFF + buf * 8192;
#pragma unroll
        for (int i = 0; i < 4; i++) {
            float4 q = aq[buf][i];
            dega[i] += (q.x + q.y) + (q.z + q.w);
            uint32_t d = base + SW64((arow8 + 32 * i) * 64 + acol * 8);
            asm volatile("st.shared.v2.b32 [%0], {%1,%2};"
                :: "r"(d), "r"(packh2(q.x, q.y)), "r"(packh2(q.z, q.w)) : "memory");
        }
    };
    auto compute32 = [&](uint32_t aA, uint32_t aB, float (*ac)[4]) {
#pragma unroll
        for (int kc = 0; kc < 2; kc++) {
            uint32_t af[4][4];
#pragma unroll
            for (int mt = 0; mt < 4; mt++)
                ldsm4(af[mt], aA + SW64((mw + mt * 16 + arow) * 64 + kc * 32 + achk));
            uint32_t bf[4][2];
#pragma unroll
            for (int np = 0; np < 2; np++) {
                uint32_t r[4];
                ldsm4(r, aB + SW64((nw + np * 16 + brow) * 64 + kc * 32 + bchk));
                bf[np * 2][0] = r[0]; bf[np * 2][1] = r[1];
                bf[np * 2 + 1][0] = r[2]; bf[np * 2 + 1][1] = r[3];
            }
#pragma unroll
            for (int mt = 0; mt < 4; mt++)
#pragma unroll
                for (int nt = 0; nt < 4; nt++)
                    mma16(ac[mt * 4 + nt], af[mt], bf[nt]);
        }
    };

    // ---- prologue ----
    ldgA(0, 0); ldgA(1, 1);
#pragma unroll
    for (int t = 0; t < BSTAGES - 1; t++) {   // B0..B6
        if (t < NTILES) cpB(t);
        asm volatile("cp.async.commit_group;" ::: "memory");
    }

    // ---- mainloop ----
    for (int t = 0; t < NTILES; t++) {
        asm volatile("cp.async.wait_group %0;" :: "n"(BSTAGES - 2) : "memory");
        stsA(t & 1);
        __syncthreads();
        if (t + BSTAGES - 1 < NTILES) cpB(t + BSTAGES - 1);
        asm volatile("cp.async.commit_group;" ::: "memory");
        if (t + 2 < NTILES) ldgA(t + 2, t & 1);
        compute32(sb + AB_OFF + (t & 1) * 8192,
                  sb + BS_OFF + (t & (BSTAGES - 1)) * 8192, acc);
    }

    // ---- deg partials + stage W^T (fp16) ----
    float* degp = (float*)(smem + DEG_OFF);   // [128 rows][8 chunks]
#pragma unroll
    for (int i = 0; i < 4; i++)
        degp[(arow8 + 32 * i) * 8 + acol] = dega[i];
#pragma unroll
    for (int i = 0; i < 8; i++) {
        int c = tid + i * NTHR;         // 0..2047 chunks of 8 halves
        int n = c >> 4, j = c & 15;
        cp16(sb + WS_OFF + (j >> 2) * 8192 + SW64(n * 64 + (j & 3) * 16),
             Wt_g + (size_t)n * Fn + j * 8);
    }
    asm volatile("cp.async.commit_group;" ::: "memory");
    __syncthreads();   // mainloop done (Ys region free), degp visible

    // ---- y = (ax + X) / (deg + 1) -> fp16 smem [4 ktiles][128m][32k] ----
#pragma unroll
    for (int mt = 0; mt < 4; mt++) {
        int m1 = mw + mt * 16 + g, m2 = m1 + 8;
        float s1 = 0.0f, s2 = 0.0f;
#pragma unroll
        for (int j = 0; j < 8; j++) { s1 += degp[m1 * 8 + j]; s2 += degp[m2 * 8 + j]; }
        float r1 = 1.0f / (s1 + 1.0f);
        float r2 = 1.0f / (s2 + 1.0f);
        const float* x1 = X + ((size_t)b * Nn + r0 + m1) * Fn;
        const float* x2 = X + ((size_t)b * Nn + r0 + m2) * Fn;
#pragma unroll
        for (int nt = 0; nt < 4; nt++) {
            int n = nw + nt * 8 + 2 * tg;
            float* c = acc[mt * 4 + nt];
            float2 xa = *(const float2*)(x1 + n);
            float2 xb = *(const float2*)(x2 + n);
            uint32_t y01 = packh2((c[0] + xa.x) * r1, (c[1] + xa.y) * r1);
            uint32_t y23 = packh2((c[2] + xb.x) * r2, (c[3] + xb.y) * r2);
            uint32_t base = sb + YS_OFF + (n >> 5) * 8192;
            asm volatile("st.shared.b32 [%0], %1;"
                         :: "r"(base + SW64(m1 * 64 + (n & 31) * 2)), "r"(y01) : "memory");
            asm volatile("st.shared.b32 [%0], %1;"
                         :: "r"(base + SW64(m2 * 64 + (n & 31) * 2)), "r"(y23) : "memory");
        }
    }
    asm volatile("cp.async.wait_group 0;" ::: "memory");
    __syncthreads();

    // ---- second GEMM: z = y @ W (M=128,N=128,K=128) ----
    float acc2[16][4];
#pragma unroll
    for (int i = 0; i < 16; i++)
#pragma unroll
        for (int j = 0; j < 4; j++) acc2[i][j] = 0.0f;
#pragma unroll
    for (int kt = 0; kt < 4; kt++)
        compute32(sb + YS_OFF + kt * 8192, sb + WS_OFF + kt * 8192, acc2);

    // ---- relu + store ----
#pragma unroll
    for (int mt = 0; mt < 4; mt++) {
        int m1 = mw + mt * 16 + g, m2 = m1 + 8;
        float* o1 = out + ((size_t)b * Nn + r0 + m1) * Fn;
        float* o2 = out + ((size_t)b * Nn + r0 + m2) * Fn;
#pragma unroll
        for (int nt = 0; nt < 4; nt++) {
            int n = nw + nt * 8 + 2 * tg;
            float* c = acc2[mt * 4 + nt];
            *(float2*)(o1 + n) = make_float2(fmaxf(c[0], 0.0f), fmaxf(c[1], 0.0f));
            *(float2*)(o2 + n) = make_float2(fmaxf(c[2], 0.0f), fmaxf(c[3], 0.0f));
        }
    }
}

// ===================== launch =====================
extern "C" void kernel_launch(void* const* d_in, const int* in_sizes, int n_in,
                              void* d_out, int out_size)
{
    const float* A = (const float*)d_in[0];
    const float* X = (const float*)d_in[1];
    const float* W = (const float*)d_in[2];
    float* out = (float*)d_out;

    static bool attr_set = false;
    if (!attr_set) {
        cudaFuncSetAttribute(graphconv_mma_kernel,
                             cudaFuncAttributeMaxDynamicSharedMemorySize, SMEM_TOTAL);
        attr_set = true;
    }

    dim3 tb(32, 8);
    prep_fused<<<dim3(Nn / 32, Fn / 32, Bn + 1), tb>>>(X, W);

    dim3 grid(Nn / 128, Bn);
    graphconv_mma_kernel<<<grid, NTHR, SMEM_TOTAL>>>(A, X, out);
}

// round 6
// speedup vs baseline: 1.4456x; 1.3908x over previous
#include <cuda_runtime.h>
#include <cuda_fp16.h>
#include <cstdint>

// GraphConv: out = relu( ((A @ X + X) / (rowsum(A)+1)) @ W )
// A: [4,4096,4096] f32, X: [4,4096,128] f32, W: [128,128] f32, out f32.
// fp16 mma.sync m16n8k16; 512 threads (16 warps) for latency hiding.

#define Bn 4
#define Nn 4096
#define Fn 128
#define KT 32
#define NTILES (Nn / KT)   // 128
#define BSTAGES 8
#define NTHR 512

// device scratch: X^T per batch [f][k] fp16, W^T [n][k] fp16
__device__ __align__(256) __half Xt_g[(size_t)Bn * Fn * Nn];
__device__ __align__(256) __half Wt_g[Fn * Fn];

// smem layout (bytes)
#define AB_OFF  0                 // 2 x 8192
#define BS_OFF  16384             // 8 x 8192
#define WS_OFF  81920             // 4 x 8192
#define DEG_OFF 114688            // 128*8*4
#define YS_OFF  0                 // reuses A/B region post-mainloop
#define SMEM_TOTAL (DEG_OFF + 4096)

#define SW64(x) ((x) ^ (((x) >> 3) & 0x30))

__device__ __forceinline__ uint32_t smem_u32(const void* p) {
    uint32_t a;
    asm("{ .reg .u64 t; cvta.to.shared.u64 t, %1; cvt.u32.u64 %0, t; }" : "=r"(a) : "l"(p));
    return a;
}
__device__ __forceinline__ void cp16(uint32_t dst, const void* src) {
    asm volatile("cp.async.cg.shared.global [%0], [%1], 16;" :: "r"(dst), "l"(src) : "memory");
}
__device__ __forceinline__ void ldsm4(uint32_t* r, uint32_t a) {
    asm volatile("ldmatrix.sync.aligned.m8n8.x4.shared.b16 {%0,%1,%2,%3}, [%4];"
                 : "=r"(r[0]), "=r"(r[1]), "=r"(r[2]), "=r"(r[3]) : "r"(a));
}
__device__ __forceinline__ void mma16(float* c, const uint32_t* a, const uint32_t* b) {
    asm volatile(
        "mma.sync.aligned.m16n8k16.row.col.f32.f16.f16.f32 "
        "{%0,%1,%2,%3},{%4,%5,%6,%7},{%8,%9},{%0,%1,%2,%3};"
        : "+f"(c[0]), "+f"(c[1]), "+f"(c[2]), "+f"(c[3])
        : "r"(a[0]), "r"(a[1]), "r"(a[2]), "r"(a[3]), "r"(b[0]), "r"(b[1]));
}
__device__ __forceinline__ uint32_t packh2(float a, float b) {
    __half2 h = __floats2half2_rn(a, b);
    return *(uint32_t*)&h;
}

// ===================== fused prep kernel =====================
__global__ void prep_fused(const float* __restrict__ X, const float* __restrict__ W) {
    __shared__ float t[32][33];
    int tx = threadIdx.x, ty = threadIdx.y;   // 32 x 8
    if (blockIdx.z < Bn) {
        int b = blockIdx.z;
        int bk = blockIdx.x * 32;
        int bn = blockIdx.y * 32;
        const float* Xb = X + (size_t)b * Nn * Fn;
        __half* Xtb = Xt_g + (size_t)b * Fn * Nn;
#pragma unroll
        for (int i = 0; i < 4; i++)
            t[ty + i * 8][tx] = Xb[(size_t)(bk + ty + i * 8) * Fn + bn + tx];
        __syncthreads();
#pragma unroll
        for (int i = 0; i < 4; i++)
            Xtb[(size_t)(bn + ty + i * 8) * Nn + bk + tx] = __float2half_rn(t[tx][ty + i * 8]);
    } else {
        if (blockIdx.x >= 4 || blockIdx.y >= 4) return;
        int bk = blockIdx.x * 32, bn = blockIdx.y * 32;
#pragma unroll
        for (int i = 0; i < 4; i++)
            t[ty + i * 8][tx] = W[(size_t)(bk + ty + i * 8) * Fn + bn + tx];
        __syncthreads();
#pragma unroll
        for (int i = 0; i < 4; i++)
            Wt_g[(size_t)(bn + ty + i * 8) * Fn + bk + tx] = __float2half_rn(t[tx][ty + i * 8]);
    }
}

// ===================== main kernel =====================
__global__ __launch_bounds__(NTHR, 1)
void graphconv_mma_kernel(const float* __restrict__ A,
                          const float* __restrict__ X,
                          float* __restrict__ out)
{
    extern __shared__ char smem[];
    const uint32_t sb = smem_u32(smem);
    const int tid = threadIdx.x;
    const int w = tid >> 5, L = tid & 31;
    const int b = blockIdx.y, r0 = blockIdx.x * 128;

    // warp tile m32 x n32 ; warps 4(m) x 4(n)
    const int mw = (w >> 2) * 32;
    const int nw = (w & 3) * 32;
    const int g = L >> 2, tg = L & 3;
    // ldsm lane offsets (fp16, 64B rows)
    const int arow = L & 15;
    const int achk = (L >> 4) * 16;
    const int brow = (L & 7) + ((L >> 4) << 3);
    const int bchk = ((L >> 3) & 1) * 16;
    // A gmem load role: 8 threads per 128B row, 16B each; 2 rows per thread
    const int arow8 = tid >> 3;   // 0..63 (+64)
    const int acol  = tid & 7;

    const float* Abase = A + ((size_t)b * Nn + r0) * Nn;
    const __half* Xth  = Xt_g + (size_t)b * Fn * Nn;

    float acc[8][4];
#pragma unroll
    for (int i = 0; i < 8; i++)
#pragma unroll
        for (int j = 0; j < 4; j++) acc[i][j] = 0.0f;

    float dega[2] = {0.0f, 0.0f};
    float4 aq[2][2];               // A prefetch, 2 tiles deep, 2 rows/thread
    const float* Aldg = Abase + (size_t)arow8 * Nn + acol * 4;

    auto ldgA = [&](int t, int buf) {
#pragma unroll
        for (int i = 0; i < 2; i++)
            aq[buf][i] = *(const float4*)(Aldg + (size_t)(64 * i) * Nn + t * KT);
    };
    auto cpB = [&](int t) {
        const int s = t & (BSTAGES - 1);
        const int k0 = t * KT;
        int n = tid >> 2, j = tid & 3;
        cp16(sb + BS_OFF + s * 8192 + SW64(n * 64 + j * 16),
             Xth + (size_t)n * Nn + k0 + j * 8);
    };
    auto stsA = [&](int buf) {
        uint32_t base = sb + AB_OFF + buf * 8192;
#pragma unroll
        for (int i = 0; i < 2; i++) {
            float4 q = aq[buf][i];
            dega[i] += (q.x + q.y) + (q.z + q.w);
            uint32_t d = base + SW64((arow8 + 64 * i) * 64 + acol * 8);
            asm volatile("st.shared.v2.b32 [%0], {%1,%2};"
                :: "r"(d), "r"(packh2(q.x, q.y)), "r"(packh2(q.z, q.w)) : "memory");
        }
    };
    auto compute32 = [&](uint32_t aA, uint32_t aB, float (*ac)[4]) {
#pragma unroll
        for (int kc = 0; kc < 2; kc++) {
            uint32_t af[2][4];
#pragma unroll
            for (int mt = 0; mt < 2; mt++)
                ldsm4(af[mt], aA + SW64((mw + mt * 16 + arow) * 64 + kc * 32 + achk));
            uint32_t bf[4][2];
#pragma unroll
            for (int np = 0; np < 2; np++) {
                uint32_t r[4];
                ldsm4(r, aB + SW64((nw + np * 16 + brow) * 64 + kc * 32 + bchk));
                bf[np * 2][0] = r[0]; bf[np * 2][1] = r[1];
                bf[np * 2 + 1][0] = r[2]; bf[np * 2 + 1][1] = r[3];
            }
#pragma unroll
            for (int mt = 0; mt < 2; mt++)
#pragma unroll
                for (int nt = 0; nt < 4; nt++)
                    mma16(ac[mt * 4 + nt], af[mt], bf[nt]);
        }
    };

    // ---- prologue ----
    ldgA(0, 0); ldgA(1, 1);
#pragma unroll
    for (int t = 0; t < BSTAGES - 1; t++) {
        if (t < NTILES) cpB(t);
        asm volatile("cp.async.commit_group;" ::: "memory");
    }

    // ---- mainloop ----
    for (int t = 0; t < NTILES; t++) {
        asm volatile("cp.async.wait_group %0;" :: "n"(BSTAGES - 2) : "memory");
        stsA(t & 1);
        __syncthreads();
        if (t + BSTAGES - 1 < NTILES) cpB(t + BSTAGES - 1);
        asm volatile("cp.async.commit_group;" ::: "memory");
        if (t + 2 < NTILES) ldgA(t + 2, t & 1);
        compute32(sb + AB_OFF + (t & 1) * 8192,
                  sb + BS_OFF + (t & (BSTAGES - 1)) * 8192, acc);
    }

    // ---- deg partials + stage W^T (fp16) ----
    float* degp = (float*)(smem + DEG_OFF);   // [128 rows][8 chunks]
#pragma unroll
    for (int i = 0; i < 2; i++)
        degp[(arow8 + 64 * i) * 8 + acol] = dega[i];
#pragma unroll
    for (int i = 0; i < 4; i++) {
        int c = tid + i * NTHR;         // 0..2047 chunks of 8 halves
        int n = c >> 4, j = c & 15;
        cp16(sb + WS_OFF + (j >> 2) * 8192 + SW64(n * 64 + (j & 3) * 16),
             Wt_g + (size_t)n * Fn + j * 8);
    }
    asm volatile("cp.async.commit_group;" ::: "memory");
    __syncthreads();   // mainloop done (Ys region free), degp visible

    // ---- y = (ax + X) / (deg + 1) -> fp16 smem [4 ktiles][128m][32k] ----
#pragma unroll
    for (int mt = 0; mt < 2; mt++) {
        int m1 = mw + mt * 16 + g, m2 = m1 + 8;
        float s1 = 0.0f, s2 = 0.0f;
#pragma unroll
        for (int j = 0; j < 8; j++) { s1 += degp[m1 * 8 + j]; s2 += degp[m2 * 8 + j]; }
        float r1 = 1.0f / (s1 + 1.0f);
        float r2 = 1.0f / (s2 + 1.0f);
        const float* x1 = X + ((size_t)b * Nn + r0 + m1) * Fn;
        const float* x2 = X + ((size_t)b * Nn + r0 + m2) * Fn;
#pragma unroll
        for (int nt = 0; nt < 4; nt++) {
            int n = nw + nt * 8 + 2 * tg;
            float* c = acc[mt * 4 + nt];
            float2 xa = *(const float2*)(x1 + n);
            float2 xb = *(const float2*)(x2 + n);
            uint32_t y01 = packh2((c[0] + xa.x) * r1, (c[1] + xa.y) * r1);
            uint32_t y23 = packh2((c[2] + xb.x) * r2, (c[3] + xb.y) * r2);
            uint32_t base = sb + YS_OFF + (n >> 5) * 8192;
            asm volatile("st.shared.b32 [%0], %1;"
                         :: "r"(base + SW64(m1 * 64 + (n & 31) * 2)), "r"(y01) : "memory");
            asm volatile("st.shared.b32 [%0], %1;"
                         :: "r"(base + SW64(m2 * 64 + (n & 31) * 2)), "r"(y23) : "memory");
        }
    }
    asm volatile("cp.async.wait_group 0;" ::: "memory");
    __syncthreads();

    // ---- second GEMM: z = y @ W (M=128,N=128,K=128) ----
    float acc2[8][4];
#pragma unroll
    for (int i = 0; i < 8; i++)
#pragma unroll
        for (int j = 0; j < 4; j++) acc2[i][j] = 0.0f;
#pragma unroll
    for (int kt = 0; kt < 4; kt++)
        compute32(sb + YS_OFF + kt * 8192, sb + WS_OFF + kt * 8192, acc2);

    // ---- relu + store ----
#pragma unroll
    for (int mt = 0; mt < 2; mt++) {
        int m1 = mw + mt * 16 + g, m2 = m1 + 8;
        float* o1 = out + ((size_t)b * Nn + r0 + m1) * Fn;
        float* o2 = out + ((size_t)b * Nn + r0 + m2) * Fn;
#pragma unroll
        for (int nt = 0; nt < 4; nt++) {
            int n = nw + nt * 8 + 2 * tg;
            float* c = acc2[mt * 4 + nt];
            *(float2*)(o1 + n) = make_float2(fmaxf(c[0], 0.0f), fmaxf(c[1], 0.0f));
            *(float2*)(o2 + n) = make_float2(fmaxf(c[2], 0.0f), fmaxf(c[3], 0.0f));
        }
    }
}

// ===================== launch =====================
extern "C" void kernel_launch(void* const* d_in, const int* in_sizes, int n_in,
                              void* d_out, int out_size)
{
    const float* A = (const float*)d_in[0];
    const float* X = (const float*)d_in[1];
    const float* W = (const float*)d_in[2];
    float* out = (float*)d_out;

    static bool attr_set = false;
    if (!attr_set) {
        cudaFuncSetAttribute(graphconv_mma_kernel,
                             cudaFuncAttributeMaxDynamicSharedMemorySize, SMEM_TOTAL);
        attr_set = true;
    }

    dim3 tb(32, 8);
    prep_fused<<<dim3(Nn / 32, Fn / 32, Bn + 1), tb>>>(X, W);

    dim3 grid(Nn / 128, Bn);
    graphconv_mma_kernel<<<grid, NTHR, SMEM_TOTAL>>>(A, X, out);
}

// round 7
// speedup vs baseline: 2.4775x; 1.7138x over previous
#include <cuda_runtime.h>
#include <cuda_fp16.h>
#include <cstdint>

// GraphConv: out = relu( ((A @ X + X) / (rowsum(A)+1)) @ W )
// A: [4,4096,4096] f32, X: [4,4096,128] f32, W: [128,128] f32, out f32.
// fp16 mma.sync m16n8k16; KT=64 tiles, 1 barrier per tile, decoupled STS.

#define Bn 4
#define Nn 4096
#define Fn 128
#define KT 64
#define NTILES (Nn / KT)   // 64
#define BSTAGES 4
#define NTHR 512

// device scratch: X^T per batch [f][k] fp16, W^T [n][k] fp16
__device__ __align__(256) __half Xt_g[(size_t)Bn * Fn * Nn];
__device__ __align__(256) __half Wt_g[Fn * Fn];

// smem layout (bytes):
//  Abuf 2 x 16384 @ 0       (Ys 2 x 16384 reuses @0 post-mainloop)
//  Bstg 4 x 16384 @ 32768   (Ws 2 x 16384 reuses stages 0-1 post-mainloop)
//  degp 128*16*4  @ 98304
#define AB_OFF  0
#define BS_OFF  32768
#define WS_OFF  32768
#define YS_OFF  0
#define DEG_OFF 98304
#define SMEM_TOTAL (DEG_OFF + 8192)

#define SW(x) ((x) ^ (((x) >> 3) & 0x70))

__device__ __forceinline__ uint32_t smem_u32(const void* p) {
    uint32_t a;
    asm("{ .reg .u64 t; cvta.to.shared.u64 t, %1; cvt.u32.u64 %0, t; }" : "=r"(a) : "l"(p));
    return a;
}
__device__ __forceinline__ void cp16(uint32_t dst, const void* src) {
    asm volatile("cp.async.cg.shared.global [%0], [%1], 16;" :: "r"(dst), "l"(src) : "memory");
}
__device__ __forceinline__ void ldsm4(uint32_t* r, uint32_t a) {
    asm volatile("ldmatrix.sync.aligned.m8n8.x4.shared.b16 {%0,%1,%2,%3}, [%4];"
                 : "=r"(r[0]), "=r"(r[1]), "=r"(r[2]), "=r"(r[3]) : "r"(a));
}
__device__ __forceinline__ void mma16(float* c, const uint32_t* a, const uint32_t* b) {
    asm volatile(
        "mma.sync.aligned.m16n8k16.row.col.f32.f16.f16.f32 "
        "{%0,%1,%2,%3},{%4,%5,%6,%7},{%8,%9},{%0,%1,%2,%3};"
        : "+f"(c[0]), "+f"(c[1]), "+f"(c[2]), "+f"(c[3])
        : "r"(a[0]), "r"(a[1]), "r"(a[2]), "r"(a[3]), "r"(b[0]), "r"(b[1]));
}
__device__ __forceinline__ uint32_t packh2(float a, float b) {
    __half2 h = __floats2half2_rn(a, b);
    return *(uint32_t*)&h;
}

// ===================== fused prep kernel =====================
__global__ void prep_fused(const float* __restrict__ X, const float* __restrict__ W) {
    __shared__ float t[32][33];
    int tx = threadIdx.x, ty = threadIdx.y;   // 32 x 8
    if (blockIdx.z < Bn) {
        int b = blockIdx.z;
        int bk = blockIdx.x * 32;
        int bn = blockIdx.y * 32;
        const float* Xb = X + (size_t)b * Nn * Fn;
        __half* Xtb = Xt_g + (size_t)b * Fn * Nn;
#pragma unroll
        for (int i = 0; i < 4; i++)
            t[ty + i * 8][tx] = Xb[(size_t)(bk + ty + i * 8) * Fn + bn + tx];
        __syncthreads();
#pragma unroll
        for (int i = 0; i < 4; i++)
            Xtb[(size_t)(bn + ty + i * 8) * Nn + bk + tx] = __float2half_rn(t[tx][ty + i * 8]);
    } else {
        if (blockIdx.x >= 4 || blockIdx.y >= 4) return;
        int bk = blockIdx.x * 32, bn = blockIdx.y * 32;
#pragma unroll
        for (int i = 0; i < 4; i++)
            t[ty + i * 8][tx] = W[(size_t)(bk + ty + i * 8) * Fn + bn + tx];
        __syncthreads();
#pragma unroll
        for (int i = 0; i < 4; i++)
            Wt_g[(size_t)(bn + ty + i * 8) * Fn + bk + tx] = __float2half_rn(t[tx][ty + i * 8]);
    }
}

// ===================== main kernel =====================
__global__ __launch_bounds__(NTHR, 1)
void graphconv_mma_kernel(const float* __restrict__ A,
                          const float* __restrict__ X,
                          float* __restrict__ out)
{
    extern __shared__ char smem[];
    const uint32_t sb = smem_u32(smem);
    const int tid = threadIdx.x;
    const int w = tid >> 5, L = tid & 31;
    const int b = blockIdx.y, r0 = blockIdx.x * 128;

    // warp tile m32 x n32 ; warps 4(m) x 4(n)
    const int mw = (w >> 2) * 32;
    const int nw = (w & 3) * 32;
    const int g = L >> 2, tg = L & 3;
    // ldsm lane offsets (fp16, 128B rows)
    const int arow = L & 15;
    const int achk = (L >> 4) * 16;
    const int brow = (L & 7) + ((L >> 4) << 3);
    const int bchk = ((L >> 3) & 1) * 16;
    // A gmem load role: 16 threads per 256B f32 row, 16B each; 4 rows/thread
    const int lrow = tid >> 4;    // 0..31 (+32i)
    const int lcol = tid & 15;    // 16B unit within row

    const float* Abase = A + ((size_t)b * Nn + r0) * Nn;
    const __half* Xth  = Xt_g + (size_t)b * Fn * Nn;

    float acc[8][4];
#pragma unroll
    for (int i = 0; i < 8; i++)
#pragma unroll
        for (int j = 0; j < 4; j++) acc[i][j] = 0.0f;

    float dega[4] = {0.0f, 0.0f, 0.0f, 0.0f};
    float4 aq[4];                 // A prefetch, 1 tile, 4 rows/thread
    const float* Aldg = Abase + (size_t)lrow * Nn + lcol * 4;

    auto ldgA = [&](int t) {
#pragma unroll
        for (int i = 0; i < 4; i++)
            aq[i] = *(const float4*)(Aldg + (size_t)(32 * i) * Nn + t * KT);
    };
    auto stsA = [&](int buf) {
        uint32_t base = sb + AB_OFF + buf * 16384;
#pragma unroll
        for (int i = 0; i < 4; i++) {
            float4 q = aq[i];
            dega[i] += (q.x + q.y) + (q.z + q.w);
            uint32_t d = base + SW((lrow + 32 * i) * 128 + lcol * 8);
            asm volatile("st.shared.v2.b32 [%0], {%1,%2};"
                :: "r"(d), "r"(packh2(q.x, q.y)), "r"(packh2(q.z, q.w)) : "memory");
        }
    };
    auto cpB = [&](int t) {
        const int s = t & (BSTAGES - 1);
        const int k0 = t * KT;
#pragma unroll
        for (int i = 0; i < 2; i++) {
            int c = tid + i * NTHR;     // 0..1023
            int n = c >> 3, j = c & 7;
            cp16(sb + BS_OFF + s * 16384 + SW(n * 128 + j * 16),
                 Xth + (size_t)n * Nn + k0 + j * 8);
        }
    };
    auto compute64 = [&](uint32_t aA, uint32_t aB, float (*ac)[4]) {
#pragma unroll
        for (int kc = 0; kc < 4; kc++) {
            uint32_t af[2][4];
#pragma unroll
            for (int mt = 0; mt < 2; mt++)
                ldsm4(af[mt], aA + SW((mw + mt * 16 + arow) * 128 + kc * 32 + achk));
            uint32_t bf[4][2];
#pragma unroll
            for (int np = 0; np < 2; np++) {
                uint32_t r[4];
                ldsm4(r, aB + SW((nw + np * 16 + brow) * 128 + kc * 32 + bchk));
                bf[np * 2][0] = r[0]; bf[np * 2][1] = r[1];
                bf[np * 2 + 1][0] = r[2]; bf[np * 2 + 1][1] = r[3];
            }
#pragma unroll
            for (int mt = 0; mt < 2; mt++)
#pragma unroll
                for (int nt = 0; nt < 4; nt++)
                    mma16(ac[mt * 4 + nt], af[mt], bf[nt]);
        }
    };

    // ---- prologue ----
    ldgA(0);
#pragma unroll
    for (int t = 0; t < BSTAGES - 1; t++) {   // B0..B2
        cpB(t);
        asm volatile("cp.async.commit_group;" ::: "memory");
    }

    // ---- mainloop: 64 tiles, one barrier each ----
    for (int t = 0; t < NTILES; t++) {
        stsA(t & 1);
        if (t + 1 < NTILES) ldgA(t + 1);
        asm volatile("cp.async.wait_group %0;" :: "n"(BSTAGES - 2) : "memory");
        __syncthreads();
        if (t + BSTAGES - 1 < NTILES) cpB(t + BSTAGES - 1);
        asm volatile("cp.async.commit_group;" ::: "memory");
        compute64(sb + AB_OFF + (t & 1) * 16384,
                  sb + BS_OFF + (t & (BSTAGES - 1)) * 16384, acc);
    }

    // ---- deg partials + stage W^T (into freed B stages 0-1) ----
    float* degp = (float*)(smem + DEG_OFF);   // [128 rows][16 chunks]
#pragma unroll
    for (int i = 0; i < 4; i++)
        degp[(lrow + 32 * i) * 16 + lcol] = dega[i];
#pragma unroll
    for (int i = 0; i < 4; i++) {
        int c = tid + i * NTHR;         // 0..2047 chunks of 8 halves
        int n = c >> 4, j = c & 15, kt = j >> 3, jj = j & 7;
        cp16(sb + WS_OFF + kt * 16384 + SW(n * 128 + jj * 16),
             Wt_g + (size_t)n * Fn + j * 8);
    }
    asm volatile("cp.async.commit_group;" ::: "memory");
    __syncthreads();   // all compute done (Ys/A region free), degp visible

    // ---- y = (ax + X) / (deg + 1) -> fp16 smem [2 ktiles][128m][64k] ----
#pragma unroll
    for (int mt = 0; mt < 2; mt++) {
        int m1 = mw + mt * 16 + g, m2 = m1 + 8;
        float s1 = 0.0f, s2 = 0.0f;
#pragma unroll
        for (int j = 0; j < 16; j++) { s1 += degp[m1 * 16 + j]; s2 += degp[m2 * 16 + j]; }
        float r1 = 1.0f / (s1 + 1.0f);
        float r2 = 1.0f / (s2 + 1.0f);
        const float* x1 = X + ((size_t)b * Nn + r0 + m1) * Fn;
        const float* x2 = X + ((size_t)b * Nn + r0 + m2) * Fn;
#pragma unroll
        for (int nt = 0; nt < 4; nt++) {
            int n = nw + nt * 8 + 2 * tg;
            float* c = acc[mt * 4 + nt];
            float2 xa = *(const float2*)(x1 + n);
            float2 xb = *(const float2*)(x2 + n);
            uint32_t y01 = packh2((c[0] + xa.x) * r1, (c[1] + xa.y) * r1);
            uint32_t y23 = packh2((c[2] + xb.x) * r2, (c[3] + xb.y) * r2);
            uint32_t base = sb + YS_OFF + (n >> 6) * 16384;
            asm volatile("st.shared.b32 [%0], %1;"
                         :: "r"(base + SW(m1 * 128 + (n & 63) * 2)), "r"(y01) : "memory");
            asm volatile("st.shared.b32 [%0], %1;"
                         :: "r"(base + SW(m2 * 128 + (n & 63) * 2)), "r"(y23) : "memory");
        }
    }
    asm volatile("cp.async.wait_group 0;" ::: "memory");
    __syncthreads();

    // ---- second GEMM: z = y @ W (M=128,N=128,K=128) ----
    float acc2[8][4];
#pragma unroll
    for (int i = 0; i < 8; i++)
#pragma unroll
        for (int j = 0; j < 4; j++) acc2[i][j] = 0.0f;
#pragma unroll
    for (int kt = 0; kt < 2; kt++)
        compute64(sb + YS_OFF + kt * 16384, sb + WS_OFF + kt * 16384, acc2);

    // ---- relu + store ----
#pragma unroll
    for (int mt = 0; mt < 2; mt++) {
        int m1 = mw + mt * 16 + g, m2 = m1 + 8;
        float* o1 = out + ((size_t)b * Nn + r0 + m1) * Fn;
        float* o2 = out + ((size_t)b * Nn + r0 + m2) * Fn;
#pragma unroll
        for (int nt = 0; nt < 4; nt++) {
            int n = nw + nt * 8 + 2 * tg;
            float* c = acc2[mt * 4 + nt];
            *(float2*)(o1 + n) = make_float2(fmaxf(c[0], 0.0f), fmaxf(c[1], 0.0f));
            *(float2*)(o2 + n) = make_float2(fmaxf(c[2], 0.0f), fmaxf(c[3], 0.0f));
        }
    }
}

// ===================== launch =====================
extern "C" void kernel_launch(void* const* d_in, const int* in_sizes, int n_in,
                              void* d_out, int out_size)
{
    const float* A = (const float*)d_in[0];
    const float* X = (const float*)d_in[1];
    const float* W = (const float*)d_in[2];
    float* out = (float*)d_out;

    static bool attr_set = false;
    if (!attr_set) {
        cudaFuncSetAttribute(graphconv_mma_kernel,
                             cudaFuncAttributeMaxDynamicSharedMemorySize, SMEM_TOTAL);
        attr_set = true;
    }

    dim3 tb(32, 8);
    prep_fused<<<dim3(Nn / 32, Fn / 32, Bn + 1), tb>>>(X, W);

    dim3 grid(Nn / 128, Bn);
    graphconv_mma_kernel<<<grid, NTHR, SMEM_TOTAL>>>(A, X, out);
}